// round 12
// baseline (speedup 1.0000x reference)
#include <cuda_runtime.h>
#include <math.h>

#define NN 100000
#define EE 1600000
#define EP 1700000      // EE + NN (with self loops)
#define IND 128
#define HH 4
#define CC 32
#define HC 128          // HH*CC
#define ED 16
#define SCAN_B 512
#define NB_SCAN ((NN + SCAN_B - 1) / SCAN_B)   // 196
#define GEMM_BLOCKS ((NN + 63) / 64)           // 1563
#define DEG_BLOCKS ((EE + 255) / 256)          // 6250

// ---------------- scratch ----------------
__device__ float g_deg[NN];
__device__ float g_mattr[NN * ED];
__device__ float g_ale1[EP * HH];
__device__ float g_ale2[EP];
__device__ float g_h1lin[NN * HC];
__device__ float g_als1[NN * HH];
__device__ float g_ald1[NN * HH];
__device__ float g_out1[NN * HC];
__device__ float g_h2lin[NN * CC];
__device__ float g_als2[NN];
__device__ float g_ald2[NN];
__device__ float g_e2[EP];           // unnormalized p for layer 2 (for alpha output)
__device__ float g_v1[ED * HH];
__device__ float g_v2[ED];
// CSR
__device__ int  g_rowptr[NN + 1];
__device__ int  g_cursor[NN];
__device__ int  g_bsum[NB_SCAN];
__device__ int  g_boff[NB_SCAN];
__device__ int2 g_csr[EP];           // (src, edge_id) per slot, grouped by dst

__device__ __forceinline__ void red4(float* addr, float4 v) {
    asm volatile("red.global.add.v4.f32 [%0], {%1,%2,%3,%4};"
                 :: "l"(addr), "f"(v.x), "f"(v.y), "f"(v.z), "f"(v.w) : "memory");
}

// ---------------- setup kernels ----------------
__global__ void k_init() {
    int i = blockIdx.x * blockDim.x + threadIdx.x;
    int stride = gridDim.x * blockDim.x;
    float4 z4 = make_float4(0.f, 0.f, 0.f, 0.f);
    for (int j = i; j < NN * ED / 4; j += stride) ((float4*)g_mattr)[j] = z4;
    for (int j = i; j < NN; j += stride) g_deg[j] = 0.f;
}

__global__ void k_v(const float* __restrict__ W1e, const float* __restrict__ a1e,
                    const float* __restrict__ W2e, const float* __restrict__ a2e) {
    int t = threadIdx.x;
    if (t < ED * HH) {
        int d = t / HH, h = t % HH;
        float s = 0.f;
        #pragma unroll
        for (int c = 0; c < CC; c++) s += W1e[d * HC + h * CC + c] * a1e[h * CC + c];
        g_v1[d * HH + h] = s;
    } else if (t < ED * HH + ED) {
        int d = t - ED * HH;
        float s = 0.f;
        #pragma unroll
        for (int c = 0; c < CC; c++) s += W2e[d * CC + c] * a2e[c];
        g_v2[d] = s;
    }
}

// ---------------- fused phase 1: gemm1 (FMA-bound) + degale (mem/atomic-bound) ----
// Interleaved block mapping: blockIdx % 5 == 0 -> gemm block (1563), else degale (6250).
__global__ void __launch_bounds__(256) k_fused1(
        const float* __restrict__ x, const float* __restrict__ W1,
        const float* __restrict__ a1s, const float* __restrict__ a1d,
        const int* __restrict__ ei, const float* __restrict__ ea) {
    __shared__ float xs[64 * IND];       // 32 KB (gemm branch only)
    int bid = blockIdx.x;
    int tid = threadIdx.x;
    if ((bid % 5) == 0 && (bid / 5) < GEMM_BLOCKS) {
        // ---- gemm1: 64 nodes/block, 8 nodes/warp, lane = 4 output cols ----
        int gb = bid / 5;
        int w = tid >> 5, l = tid & 31;
        int base = gb * 64;
        const float4* xv4 = (const float4*)x;
        #pragma unroll
        for (int i = 0; i < 8; i++) {
            int j = tid + i * 256;
            long long gi = (long long)base * 32 + j;
            ((float4*)xs)[j] = (gi < (long long)NN * 32) ? xv4[gi] : make_float4(0.f,0.f,0.f,0.f);
        }
        __syncthreads();
        float4 acc[8];
        #pragma unroll
        for (int i = 0; i < 8; i++) acc[i] = make_float4(0.f,0.f,0.f,0.f);
        const float4* W1v = (const float4*)W1;
        #pragma unroll 2
        for (int k4 = 0; k4 < 32; k4++) {
            float4 w0 = W1v[(k4 * 4 + 0) * 32 + l];
            float4 w1 = W1v[(k4 * 4 + 1) * 32 + l];
            float4 w2 = W1v[(k4 * 4 + 2) * 32 + l];
            float4 w3 = W1v[(k4 * 4 + 3) * 32 + l];
            #pragma unroll
            for (int i = 0; i < 8; i++) {
                float4 xv = ((const float4*)xs)[(w * 8 + i) * 32 + k4];
                acc[i].x += xv.x * w0.x + xv.y * w1.x + xv.z * w2.x + xv.w * w3.x;
                acc[i].y += xv.x * w0.y + xv.y * w1.y + xv.z * w2.y + xv.w * w3.y;
                acc[i].z += xv.x * w0.z + xv.y * w1.z + xv.z * w2.z + xv.w * w3.z;
                acc[i].w += xv.x * w0.w + xv.y * w1.w + xv.z * w2.w + xv.w * w3.w;
            }
        }
        float4 as = ((const float4*)a1s)[l];
        float4 ad = ((const float4*)a1d)[l];
        #pragma unroll
        for (int i = 0; i < 8; i++) {
            int n = base + w * 8 + i;
            if (n >= NN) break;
            ((float4*)g_h1lin)[(long long)n * 32 + l] = acc[i];
            float ps = acc[i].x * as.x + acc[i].y * as.y + acc[i].z * as.z + acc[i].w * as.w;
            float pd = acc[i].x * ad.x + acc[i].y * ad.y + acc[i].z * ad.z + acc[i].w * ad.w;
            #pragma unroll
            for (int o = 4; o > 0; o >>= 1) {
                ps += __shfl_down_sync(0xffffffffu, ps, o);
                pd += __shfl_down_sync(0xffffffffu, pd, o);
            }
            if ((l & 7) == 0) {
                g_als1[n * HH + (l >> 3)] = ps;
                g_ald1[n * HH + (l >> 3)] = pd;
            }
        }
    } else {
        // ---- degale: per real edge, deg/mattr accumulation + edge dots ----
        int db = bid - bid / 5 - 1;               // 0..6249
        int e = db * 256 + tid;
        if (e >= EE) return;
        int d = ei[EE + e];
        const float4* av4 = (const float4*)(ea + (long long)e * ED);
        float4 a0 = av4[0], a1 = av4[1], a2 = av4[2], a3 = av4[3];
        red4(&g_mattr[d * ED + 0],  a0);
        red4(&g_mattr[d * ED + 4],  a1);
        red4(&g_mattr[d * ED + 8],  a2);
        red4(&g_mattr[d * ED + 12], a3);
        atomicAdd(&g_deg[d], 1.f);
        float a[ED] = {a0.x,a0.y,a0.z,a0.w, a1.x,a1.y,a1.z,a1.w,
                       a2.x,a2.y,a2.z,a2.w, a3.x,a3.y,a3.z,a3.w};
        float s0 = 0.f, s1 = 0.f, s2 = 0.f, s3 = 0.f, sv = 0.f;
        #pragma unroll
        for (int k = 0; k < ED; k++) {
            float av = a[k];
            s0 += av * g_v1[k * HH + 0];
            s1 += av * g_v1[k * HH + 1];
            s2 += av * g_v1[k * HH + 2];
            s3 += av * g_v1[k * HH + 3];
            sv += av * g_v2[k];
        }
        ((float4*)g_ale1)[e] = make_float4(s0, s1, s2, s3);
        g_ale2[e] = sv;
    }
}

// ---------------- CSR build (scan1 also does the self-loop edge dots) ----------------
__global__ void k_scan1() {
    __shared__ int sh[SCAN_B];
    int tid = threadIdx.x;
    int n = blockIdx.x * SCAN_B + tid;
    float degf = (n < NN) ? g_deg[n] : 0.f;
    int c = (n < NN) ? ((int)degf + 1) : 0;       // +1 self loop
    sh[tid] = c;
    // self-loop edge dots: dot(sum_attr, v) / max(deg,1)  (linearity => no mean pass)
    if (n < NN) {
        const float* a = g_mattr + (long long)n * ED;
        float s0 = 0.f, s1 = 0.f, s2 = 0.f, s3 = 0.f, sv = 0.f;
        #pragma unroll
        for (int k = 0; k < ED; k++) {
            float av = a[k];
            s0 += av * g_v1[k * HH + 0];
            s1 += av * g_v1[k * HH + 1];
            s2 += av * g_v1[k * HH + 2];
            s3 += av * g_v1[k * HH + 3];
            sv += av * g_v2[k];
        }
        float invd = 1.f / fmaxf(degf, 1.f);
        ((float4*)g_ale1)[EE + n] = make_float4(s0 * invd, s1 * invd, s2 * invd, s3 * invd);
        g_ale2[EE + n] = sv * invd;
    }
    __syncthreads();
    #pragma unroll
    for (int o = 1; o < SCAN_B; o <<= 1) {
        int v = (tid >= o) ? sh[tid - o] : 0;
        __syncthreads();
        sh[tid] += v;
        __syncthreads();
    }
    if (n < NN) g_rowptr[n] = sh[tid] - c;        // exclusive
    if (tid == SCAN_B - 1) g_bsum[blockIdx.x] = sh[tid];
}

__global__ void k_scan2() {
    __shared__ int sh[256];
    int tid = threadIdx.x;
    int c = (tid < NB_SCAN) ? g_bsum[tid] : 0;
    sh[tid] = c;
    __syncthreads();
    #pragma unroll
    for (int o = 1; o < 256; o <<= 1) {
        int v = (tid >= o) ? sh[tid - o] : 0;
        __syncthreads();
        sh[tid] += v;
        __syncthreads();
    }
    if (tid < NB_SCAN) g_boff[tid] = sh[tid] - c; // exclusive
}

__global__ void k_scan3() {
    int n = blockIdx.x * blockDim.x + threadIdx.x;
    if (n < NN) {
        int rp = g_rowptr[n] + g_boff[n / SCAN_B];
        g_rowptr[n] = rp;
        g_cursor[n] = rp;                          // fill's atomic cursor starts at row base
    }
    if (n == 0) g_rowptr[NN] = EP;
}

// CSR fill; also emits the edge_index float output (saves the tail's ei re-read)
__global__ void k_fill(const int* __restrict__ ei, float* __restrict__ out, int has_idx) {
    int e = blockIdx.x * blockDim.x + threadIdx.x;
    if (e >= EP) return;
    int s, d;
    if (e < EE) { s = ei[e]; d = ei[EE + e]; } else { s = d = e - EE; }
    int slot = atomicAdd(&g_cursor[d], 1);
    g_csr[slot] = make_int2(s, e);
    if (has_idx) {
        out[(long long)NN * CC + e] = (float)s;
        out[(long long)NN * CC + EP + e] = (float)d;
    }
}

// ---------------- layer 1 aggregation ----------------
// fused softmax + aggregation, warp per dst node (atomic-free)
__global__ void __launch_bounds__(256) k_agg1() {
    __shared__ int   ss[8 * 32];
    __shared__ float sp[8 * 32 * 4];
    int tid = threadIdx.x;
    int w = tid >> 5, l = tid & 31;
    int n = blockIdx.x * 8 + w;
    if (n >= NN) return;
    int start = g_rowptr[n], end = g_rowptr[n + 1];
    float4 ad = ((const float4*)g_ald1)[n];
    int h = l >> 3;
    float4 z = make_float4(0.f, 0.f, 0.f, 0.f);
    float4 acc = make_float4(0.f, 0.f, 0.f, 0.f);
    for (int base = start; base < end; base += 32) {
        int j = base + l;
        float4 p = make_float4(0.f, 0.f, 0.f, 0.f);
        int s = 0;
        if (j < end) {
            int2 cs = g_csr[j];
            s = cs.x;
            float4 as = ((const float4*)g_als1)[cs.x];
            float4 ae = ((const float4*)g_ale1)[cs.y];
            float v;
            v = as.x + ad.x + ae.x; v = (v > 0.f) ? v : 0.2f * v; p.x = __expf(v);
            v = as.y + ad.y + ae.y; v = (v > 0.f) ? v : 0.2f * v; p.y = __expf(v);
            v = as.z + ad.z + ae.z; v = (v > 0.f) ? v : 0.2f * v; p.z = __expf(v);
            v = as.w + ad.w + ae.w; v = (v > 0.f) ? v : 0.2f * v; p.w = __expf(v);
            z.x += p.x; z.y += p.y; z.z += p.z; z.w += p.w;
        }
        ss[w * 32 + l] = s;
        ((float4*)sp)[w * 32 + l] = p;
        __syncwarp();
        int cnt = min(32, end - base);
        #pragma unroll 4
        for (int t = 0; t < cnt; t++) {
            int sv = ss[w * 32 + t];
            float pw = sp[(w * 32 + t) * 4 + h];
            float4 hv = ((const float4*)g_h1lin)[(long long)sv * 32 + l];
            acc.x += pw * hv.x; acc.y += pw * hv.y;
            acc.z += pw * hv.z; acc.w += pw * hv.w;
        }
        __syncwarp();
    }
    #pragma unroll
    for (int o = 16; o > 0; o >>= 1) {
        z.x += __shfl_xor_sync(0xffffffffu, z.x, o);
        z.y += __shfl_xor_sync(0xffffffffu, z.y, o);
        z.z += __shfl_xor_sync(0xffffffffu, z.z, o);
        z.w += __shfl_xor_sync(0xffffffffu, z.w, o);
    }
    float zh = (h == 0) ? z.x : (h == 1) ? z.y : (h == 2) ? z.z : z.w;
    float inv = 1.f / zh;
    acc.x *= inv; acc.y *= inv; acc.z *= inv; acc.w *= inv;
    ((float4*)g_out1)[(long long)n * 32 + l] = acc;
}

// ---------------- layer 2 ----------------
// 32 nodes/block, 4 nodes/warp: ELU epilogue + 128x32 GEMV + logits
__global__ void __launch_bounds__(256) k_node2(
        const float* __restrict__ b1, const float* __restrict__ W2,
        const float* __restrict__ a2s, const float* __restrict__ a2d) {
    __shared__ float hs[32 * HC];
    int tid = threadIdx.x;
    int w = tid >> 5, l = tid & 31;
    int base = blockIdx.x * 32;
    #pragma unroll
    for (int i = 0; i < 4; i++) {
        int j = tid + i * 256;
        float4 v = ((const float4*)g_out1)[(long long)base * 32 + j];
        float4 bb = ((const float4*)b1)[j & 31];
        v.x += bb.x; v.y += bb.y; v.z += bb.z; v.w += bb.w;
        v.x = (v.x > 0.f) ? v.x : (__expf(v.x) - 1.f);
        v.y = (v.y > 0.f) ? v.y : (__expf(v.y) - 1.f);
        v.z = (v.z > 0.f) ? v.z : (__expf(v.z) - 1.f);
        v.w = (v.w > 0.f) ? v.w : (__expf(v.w) - 1.f);
        ((float4*)hs)[j] = v;
    }
    __syncthreads();
    float acc[4] = {0.f, 0.f, 0.f, 0.f};
    #pragma unroll 4
    for (int k4 = 0; k4 < 32; k4++) {
        float w0 = W2[(k4 * 4 + 0) * 32 + l];
        float w1 = W2[(k4 * 4 + 1) * 32 + l];
        float w2v = W2[(k4 * 4 + 2) * 32 + l];
        float w3 = W2[(k4 * 4 + 3) * 32 + l];
        #pragma unroll
        for (int i = 0; i < 4; i++) {
            float4 xv = ((const float4*)hs)[(w * 4 + i) * 32 + k4];
            acc[i] += xv.x * w0 + xv.y * w1 + xv.z * w2v + xv.w * w3;
        }
    }
    float cs = a2s[l], cd = a2d[l];
    #pragma unroll
    for (int i = 0; i < 4; i++) {
        int n = base + w * 4 + i;
        float a = acc[i];
        g_h2lin[(long long)n * CC + l] = a;
        float ps = a * cs;
        float pd = a * cd;
        #pragma unroll
        for (int o = 16; o > 0; o >>= 1) {
            ps += __shfl_down_sync(0xffffffffu, ps, o);
            pd += __shfl_down_sync(0xffffffffu, pd, o);
        }
        if (l == 0) { g_als2[n] = ps; g_ald2[n] = pd; }
    }
}

// fused softmax + aggregation + bias + ELU + alpha output, warp per dst node
__global__ void __launch_bounds__(256) k_agg2(const float* __restrict__ b2,
                                              float* __restrict__ out, int has_alpha) {
    __shared__ int   ss[8 * 32];
    __shared__ float sp[8 * 32];
    int tid = threadIdx.x;
    int w = tid >> 5, l = tid & 31;
    int n = blockIdx.x * 8 + w;
    if (n >= NN) return;
    int start = g_rowptr[n], end = g_rowptr[n + 1];
    float ad = g_ald2[n];
    int g = l >> 3, q = l & 7;
    float z = 0.f;
    float4 acc = make_float4(0.f, 0.f, 0.f, 0.f);
    for (int base = start; base < end; base += 32) {
        int j = base + l;
        float p = 0.f;
        int s = 0;
        if (j < end) {
            int2 cs = g_csr[j];
            s = cs.x;
            float v = g_als2[cs.x] + ad + g_ale2[cs.y];
            v = (v > 0.f) ? v : 0.2f * v;
            p = __expf(v);
            z += p;
            g_e2[cs.y] = p;                 // unnormalized; rescaled below
        }
        ss[w * 32 + l] = s;
        sp[w * 32 + l] = p;
        __syncwarp();
        int cnt = min(32, end - base);
        for (int t4 = 0; t4 < cnt; t4 += 4) {
            int t = t4 + g;
            if (t < cnt) {
                int sv = ss[w * 32 + t];
                float pw = sp[w * 32 + t];
                float4 hv = ((const float4*)g_h2lin)[(long long)sv * 8 + q];
                acc.x += pw * hv.x; acc.y += pw * hv.y;
                acc.z += pw * hv.z; acc.w += pw * hv.w;
            }
        }
        __syncwarp();
    }
    #pragma unroll
    for (int o = 16; o > 0; o >>= 1) z += __shfl_xor_sync(0xffffffffu, z, o);
    float inv = 1.f / z;
    // alpha output: rescale this node's unnormalized p's (csr/e2 hot in cache)
    if (has_alpha) {
        for (int j = start + l; j < end; j += 32) {
            int eid = g_csr[j].y;
            out[(long long)NN * CC + 2LL * EP + eid] = g_e2[eid] * inv;
        }
    }
    acc.x += __shfl_xor_sync(0xffffffffu, acc.x, 8);
    acc.y += __shfl_xor_sync(0xffffffffu, acc.y, 8);
    acc.z += __shfl_xor_sync(0xffffffffu, acc.z, 8);
    acc.w += __shfl_xor_sync(0xffffffffu, acc.w, 8);
    acc.x += __shfl_xor_sync(0xffffffffu, acc.x, 16);
    acc.y += __shfl_xor_sync(0xffffffffu, acc.y, 16);
    acc.z += __shfl_xor_sync(0xffffffffu, acc.z, 16);
    acc.w += __shfl_xor_sync(0xffffffffu, acc.w, 16);
    if (l < 8) {
        float4 bb = ((const float4*)b2)[q];
        float4 o4;
        o4.x = acc.x * inv + bb.x; o4.x = (o4.x > 0.f) ? o4.x : (__expf(o4.x) - 1.f);
        o4.y = acc.y * inv + bb.y; o4.y = (o4.y > 0.f) ? o4.y : (__expf(o4.y) - 1.f);
        o4.z = acc.z * inv + bb.z; o4.z = (o4.z > 0.f) ? o4.z : (__expf(o4.z) - 1.f);
        o4.w = acc.w * inv + bb.w; o4.w = (o4.w > 0.f) ? o4.w : (__expf(o4.w) - 1.f);
        ((float4*)out)[(long long)n * 8 + q] = o4;
    }
}

extern "C" void kernel_launch(void* const* d_in, const int* in_sizes, int n_in,
                              void* d_out, int out_size) {
    const float* x    = (const float*)d_in[0];
    const int*   ei   = (const int*)d_in[1];
    const float* ea   = (const float*)d_in[2];
    const float* W1   = (const float*)d_in[3];
    const float* W1e  = (const float*)d_in[4];
    const float* a1s  = (const float*)d_in[5];
    const float* a1d  = (const float*)d_in[6];
    const float* a1e  = (const float*)d_in[7];
    const float* b1   = (const float*)d_in[8];
    const float* W2   = (const float*)d_in[9];
    const float* W2e  = (const float*)d_in[10];
    const float* a2s  = (const float*)d_in[11];
    const float* a2d  = (const float*)d_in[12];
    const float* a2e  = (const float*)d_in[13];
    const float* b2   = (const float*)d_in[14];
    float* out = (float*)d_out;

    int has_idx   = (out_size >= NN * CC + 2 * EP) ? 1 : 0;
    int has_alpha = (out_size >= NN * CC + 2 * EP + EP) ? 1 : 0;

    k_init<<<512, 256>>>();
    k_v<<<1, 96>>>(W1e, a1e, W2e, a2e);
    k_fused1<<<GEMM_BLOCKS + DEG_BLOCKS, 256>>>(x, W1, a1s, a1d, ei, ea);
    k_scan1<<<NB_SCAN, SCAN_B>>>();
    k_scan2<<<1, 256>>>();
    k_scan3<<<(NN + 255) / 256, 256>>>();
    k_fill<<<(EP + 255) / 256, 256>>>(ei, out, has_idx);
    k_agg1<<<(NN + 7) / 8, 256>>>();
    k_node2<<<(NN + 31) / 32, 256>>>(b1, W2, a2s, a2d);
    k_agg2<<<(NN + 7) / 8, 256>>>(b2, out, has_alpha);
}

// round 13
// speedup vs baseline: 1.0983x; 1.0983x over previous
#include <cuda_runtime.h>
#include <math.h>

#define NN 100000
#define EE 1600000
#define EP 1700000      // EE + NN (with self loops)
#define IND 128
#define HH 4
#define CC 32
#define HC 128          // HH*CC
#define ED 16
#define SCAN_B 512
#define NB_SCAN ((NN + SCAN_B - 1) / SCAN_B)   // 196
#define GEMM_BLOCKS ((NN + 63) / 64)           // 1563
#define DEG_BLOCKS ((EE + 255) / 256)          // 6250

// ---------------- scratch ----------------
__device__ float  g_alacc[NN * HH];   // per-dst sum of edge head-dots (layer 1)
__device__ float2 g_svd[NN];          // per-dst (sum of layer-2 edge dots, degree)
__device__ float g_ale1[EP * HH];
__device__ float g_ale2[EP];
__device__ float g_h1lin[NN * HC];
__device__ float g_als1[NN * HH];
__device__ float g_ald1[NN * HH];
__device__ float g_out1[NN * HC];
__device__ float g_h2lin[NN * CC];
__device__ float g_als2[NN];
__device__ float g_ald2[NN];
__device__ float g_z2[NN];
__device__ float g_e2[EP];           // unnormalized p for layer 2 (for alpha output)
__device__ float g_v1[ED * HH];
__device__ float g_v2[ED];
// CSR
__device__ int  g_rowptr[NN + 1];
__device__ int  g_cursor[NN];
__device__ int  g_bsum[NB_SCAN];
__device__ int  g_boff[NB_SCAN];
__device__ int2 g_csr[EP];           // (src, edge_id) per slot, grouped by dst

__device__ __forceinline__ void red4(float* addr, float4 v) {
    asm volatile("red.global.add.v4.f32 [%0], {%1,%2,%3,%4};"
                 :: "l"(addr), "f"(v.x), "f"(v.y), "f"(v.z), "f"(v.w) : "memory");
}
__device__ __forceinline__ void red2(float2* addr, float2 v) {
    asm volatile("red.global.add.v2.f32 [%0], {%1,%2};"
                 :: "l"(addr), "f"(v.x), "f"(v.y) : "memory");
}

// ---------------- setup kernels ----------------
__global__ void k_init() {
    int i = blockIdx.x * blockDim.x + threadIdx.x;
    int stride = gridDim.x * blockDim.x;
    float4 z4 = make_float4(0.f, 0.f, 0.f, 0.f);
    for (int j = i; j < NN; j += stride) {
        ((float4*)g_alacc)[j] = z4;
        g_svd[j] = make_float2(0.f, 0.f);
    }
}

__global__ void k_v(const float* __restrict__ W1e, const float* __restrict__ a1e,
                    const float* __restrict__ W2e, const float* __restrict__ a2e) {
    int t = threadIdx.x;
    if (t < ED * HH) {
        int d = t / HH, h = t % HH;
        float s = 0.f;
        #pragma unroll
        for (int c = 0; c < CC; c++) s += W1e[d * HC + h * CC + c] * a1e[h * CC + c];
        g_v1[d * HH + h] = s;
    } else if (t < ED * HH + ED) {
        int d = t - ED * HH;
        float s = 0.f;
        #pragma unroll
        for (int c = 0; c < CC; c++) s += W2e[d * CC + c] * a2e[c];
        g_v2[d] = s;
    }
}

// ---------------- fused phase 1: gemm1 (FMA-bound) + degale (mem/atomic-bound) ----
// Interleaved block mapping: blockIdx % 5 == 0 -> gemm block (1563), else degale (6250).
__global__ void __launch_bounds__(256) k_fused1(
        const float* __restrict__ x, const float* __restrict__ W1,
        const float* __restrict__ a1s, const float* __restrict__ a1d,
        const int* __restrict__ ei, const float* __restrict__ ea) {
    __shared__ float xs[64 * IND];       // 32 KB (gemm branch only)
    int bid = blockIdx.x;
    int tid = threadIdx.x;
    if ((bid % 5) == 0 && (bid / 5) < GEMM_BLOCKS) {
        // ---- gemm1: 64 nodes/block, 8 nodes/warp, lane = 4 output cols ----
        int gb = bid / 5;
        int w = tid >> 5, l = tid & 31;
        int base = gb * 64;
        const float4* xv4 = (const float4*)x;
        #pragma unroll
        for (int i = 0; i < 8; i++) {
            int j = tid + i * 256;
            long long gi = (long long)base * 32 + j;
            ((float4*)xs)[j] = (gi < (long long)NN * 32) ? xv4[gi] : make_float4(0.f,0.f,0.f,0.f);
        }
        __syncthreads();
        float4 acc[8];
        #pragma unroll
        for (int i = 0; i < 8; i++) acc[i] = make_float4(0.f,0.f,0.f,0.f);
        const float4* W1v = (const float4*)W1;
        #pragma unroll 2
        for (int k4 = 0; k4 < 32; k4++) {
            float4 w0 = W1v[(k4 * 4 + 0) * 32 + l];
            float4 w1 = W1v[(k4 * 4 + 1) * 32 + l];
            float4 w2 = W1v[(k4 * 4 + 2) * 32 + l];
            float4 w3 = W1v[(k4 * 4 + 3) * 32 + l];
            #pragma unroll
            for (int i = 0; i < 8; i++) {
                float4 xv = ((const float4*)xs)[(w * 8 + i) * 32 + k4];
                acc[i].x += xv.x * w0.x + xv.y * w1.x + xv.z * w2.x + xv.w * w3.x;
                acc[i].y += xv.x * w0.y + xv.y * w1.y + xv.z * w2.y + xv.w * w3.y;
                acc[i].z += xv.x * w0.z + xv.y * w1.z + xv.z * w2.z + xv.w * w3.z;
                acc[i].w += xv.x * w0.w + xv.y * w1.w + xv.z * w2.w + xv.w * w3.w;
            }
        }
        float4 as = ((const float4*)a1s)[l];
        float4 ad = ((const float4*)a1d)[l];
        #pragma unroll
        for (int i = 0; i < 8; i++) {
            int n = base + w * 8 + i;
            if (n >= NN) break;
            ((float4*)g_h1lin)[(long long)n * 32 + l] = acc[i];
            float ps = acc[i].x * as.x + acc[i].y * as.y + acc[i].z * as.z + acc[i].w * as.w;
            float pd = acc[i].x * ad.x + acc[i].y * ad.y + acc[i].z * ad.z + acc[i].w * ad.w;
            #pragma unroll
            for (int o = 4; o > 0; o >>= 1) {
                ps += __shfl_down_sync(0xffffffffu, ps, o);
                pd += __shfl_down_sync(0xffffffffu, pd, o);
            }
            if ((l & 7) == 0) {
                g_als1[n * HH + (l >> 3)] = ps;
                g_ald1[n * HH + (l >> 3)] = pd;
            }
        }
    } else {
        // ---- degale: per real edge, edge dots; accumulate the DOTS per dst
        //      (linearity: dot(mean_attr,v) = (sum_e dot(attr_e,v)) / deg)
        int db = bid - bid / 5 - 1;               // 0..6249
        int e = db * 256 + tid;
        if (e >= EE) return;
        int d = ei[EE + e];
        const float4* av4 = (const float4*)(ea + (long long)e * ED);
        float4 a0 = av4[0], a1 = av4[1], a2 = av4[2], a3 = av4[3];
        float a[ED] = {a0.x,a0.y,a0.z,a0.w, a1.x,a1.y,a1.z,a1.w,
                       a2.x,a2.y,a2.z,a2.w, a3.x,a3.y,a3.z,a3.w};
        float s0 = 0.f, s1 = 0.f, s2 = 0.f, s3 = 0.f, sv = 0.f;
        #pragma unroll
        for (int k = 0; k < ED; k++) {
            float av = a[k];
            s0 += av * g_v1[k * HH + 0];
            s1 += av * g_v1[k * HH + 1];
            s2 += av * g_v1[k * HH + 2];
            s3 += av * g_v1[k * HH + 3];
            sv += av * g_v2[k];
        }
        float4 s4 = make_float4(s0, s1, s2, s3);
        ((float4*)g_ale1)[e] = s4;
        g_ale2[e] = sv;
        red4(&g_alacc[d * HH], s4);
        red2(&g_svd[d], make_float2(sv, 1.f));
    }
}

// self-loop edge dots from accumulated per-dst dot sums
__global__ void k_ale_self() {
    int n = blockIdx.x * blockDim.x + threadIdx.x;
    if (n >= NN) return;
    float2 svd = g_svd[n];
    float invd = 1.f / fmaxf(svd.y, 1.f);
    float4 s = ((const float4*)g_alacc)[n];
    ((float4*)g_ale1)[EE + n] = make_float4(s.x * invd, s.y * invd, s.z * invd, s.w * invd);
    g_ale2[EE + n] = svd.x * invd;
}

// ---------------- CSR build ----------------
__global__ void k_scan1() {
    __shared__ int sh[SCAN_B];
    int tid = threadIdx.x;
    int n = blockIdx.x * SCAN_B + tid;
    int c = (n < NN) ? ((int)g_svd[n].y + 1) : 0;   // +1 self loop
    sh[tid] = c;
    __syncthreads();
    #pragma unroll
    for (int o = 1; o < SCAN_B; o <<= 1) {
        int v = (tid >= o) ? sh[tid - o] : 0;
        __syncthreads();
        sh[tid] += v;
        __syncthreads();
    }
    if (n < NN) g_rowptr[n] = sh[tid] - c;        // exclusive
    if (tid == SCAN_B - 1) g_bsum[blockIdx.x] = sh[tid];
}

__global__ void k_scan2() {
    __shared__ int sh[256];
    int tid = threadIdx.x;
    int c = (tid < NB_SCAN) ? g_bsum[tid] : 0;
    sh[tid] = c;
    __syncthreads();
    #pragma unroll
    for (int o = 1; o < 256; o <<= 1) {
        int v = (tid >= o) ? sh[tid - o] : 0;
        __syncthreads();
        sh[tid] += v;
        __syncthreads();
    }
    if (tid < NB_SCAN) g_boff[tid] = sh[tid] - c; // exclusive
}

__global__ void k_scan3() {
    int n = blockIdx.x * blockDim.x + threadIdx.x;
    if (n < NN) {
        int rp = g_rowptr[n] + g_boff[n / SCAN_B];
        g_rowptr[n] = rp;
        g_cursor[n] = rp;                          // fill's atomic cursor starts at row base
    }
    if (n == 0) g_rowptr[NN] = EP;
}

__global__ void k_fill(const int* __restrict__ ei) {
    int e = blockIdx.x * blockDim.x + threadIdx.x;
    if (e >= EP) return;
    int s, d;
    if (e < EE) { s = ei[e]; d = ei[EE + e]; } else { s = d = e - EE; }
    int slot = atomicAdd(&g_cursor[d], 1);
    g_csr[slot] = make_int2(s, e);
}

// ---------------- layer 1 aggregation ----------------
// fused softmax + aggregation, warp per dst node (atomic-free)
__global__ void __launch_bounds__(256) k_agg1() {
    __shared__ int   ss[8 * 32];
    __shared__ float sp[8 * 32 * 4];
    int tid = threadIdx.x;
    int w = tid >> 5, l = tid & 31;
    int n = blockIdx.x * 8 + w;
    if (n >= NN) return;
    int start = g_rowptr[n], end = g_rowptr[n + 1];
    float4 ad = ((const float4*)g_ald1)[n];
    int h = l >> 3;
    float4 z = make_float4(0.f, 0.f, 0.f, 0.f);
    float4 acc = make_float4(0.f, 0.f, 0.f, 0.f);
    for (int base = start; base < end; base += 32) {
        int j = base + l;
        float4 p = make_float4(0.f, 0.f, 0.f, 0.f);
        int s = 0;
        if (j < end) {
            int2 cs = g_csr[j];
            s = cs.x;
            float4 as = ((const float4*)g_als1)[cs.x];
            float4 ae = ((const float4*)g_ale1)[cs.y];
            float v;
            v = as.x + ad.x + ae.x; v = (v > 0.f) ? v : 0.2f * v; p.x = __expf(v);
            v = as.y + ad.y + ae.y; v = (v > 0.f) ? v : 0.2f * v; p.y = __expf(v);
            v = as.z + ad.z + ae.z; v = (v > 0.f) ? v : 0.2f * v; p.z = __expf(v);
            v = as.w + ad.w + ae.w; v = (v > 0.f) ? v : 0.2f * v; p.w = __expf(v);
            z.x += p.x; z.y += p.y; z.z += p.z; z.w += p.w;
        }
        ss[w * 32 + l] = s;
        ((float4*)sp)[w * 32 + l] = p;
        __syncwarp();
        int cnt = min(32, end - base);
        #pragma unroll 4
        for (int t = 0; t < cnt; t++) {
            int sv = ss[w * 32 + t];
            float pw = sp[(w * 32 + t) * 4 + h];
            float4 hv = ((const float4*)g_h1lin)[(long long)sv * 32 + l];
            acc.x += pw * hv.x; acc.y += pw * hv.y;
            acc.z += pw * hv.z; acc.w += pw * hv.w;
        }
        __syncwarp();
    }
    #pragma unroll
    for (int o = 16; o > 0; o >>= 1) {
        z.x += __shfl_xor_sync(0xffffffffu, z.x, o);
        z.y += __shfl_xor_sync(0xffffffffu, z.y, o);
        z.z += __shfl_xor_sync(0xffffffffu, z.z, o);
        z.w += __shfl_xor_sync(0xffffffffu, z.w, o);
    }
    float zh = (h == 0) ? z.x : (h == 1) ? z.y : (h == 2) ? z.z : z.w;
    float inv = 1.f / zh;
    acc.x *= inv; acc.y *= inv; acc.z *= inv; acc.w *= inv;
    ((float4*)g_out1)[(long long)n * 32 + l] = acc;
}

// ---------------- layer 2 ----------------
// 32 nodes/block, 4 nodes/warp: ELU epilogue + 128x32 GEMV + logits
__global__ void __launch_bounds__(256) k_node2(
        const float* __restrict__ b1, const float* __restrict__ W2,
        const float* __restrict__ a2s, const float* __restrict__ a2d) {
    __shared__ float hs[32 * HC];
    int tid = threadIdx.x;
    int w = tid >> 5, l = tid & 31;
    int base = blockIdx.x * 32;
    #pragma unroll
    for (int i = 0; i < 4; i++) {
        int j = tid + i * 256;
        float4 v = ((const float4*)g_out1)[(long long)base * 32 + j];
        float4 bb = ((const float4*)b1)[j & 31];
        v.x += bb.x; v.y += bb.y; v.z += bb.z; v.w += bb.w;
        v.x = (v.x > 0.f) ? v.x : (__expf(v.x) - 1.f);
        v.y = (v.y > 0.f) ? v.y : (__expf(v.y) - 1.f);
        v.z = (v.z > 0.f) ? v.z : (__expf(v.z) - 1.f);
        v.w = (v.w > 0.f) ? v.w : (__expf(v.w) - 1.f);
        ((float4*)hs)[j] = v;
    }
    __syncthreads();
    float acc[4] = {0.f, 0.f, 0.f, 0.f};
    #pragma unroll 4
    for (int k4 = 0; k4 < 32; k4++) {
        float w0 = W2[(k4 * 4 + 0) * 32 + l];
        float w1 = W2[(k4 * 4 + 1) * 32 + l];
        float w2v = W2[(k4 * 4 + 2) * 32 + l];
        float w3 = W2[(k4 * 4 + 3) * 32 + l];
        #pragma unroll
        for (int i = 0; i < 4; i++) {
            float4 xv = ((const float4*)hs)[(w * 4 + i) * 32 + k4];
            acc[i] += xv.x * w0 + xv.y * w1 + xv.z * w2v + xv.w * w3;
        }
    }
    float cs = a2s[l], cd = a2d[l];
    #pragma unroll
    for (int i = 0; i < 4; i++) {
        int n = base + w * 4 + i;
        float a = acc[i];
        g_h2lin[(long long)n * CC + l] = a;
        float ps = a * cs;
        float pd = a * cd;
        #pragma unroll
        for (int o = 16; o > 0; o >>= 1) {
            ps += __shfl_down_sync(0xffffffffu, ps, o);
            pd += __shfl_down_sync(0xffffffffu, pd, o);
        }
        if (l == 0) { g_als2[n] = ps; g_ald2[n] = pd; }
    }
}

// fused softmax + aggregation + bias + ELU, warp per dst node; 8-lane edge groups
__global__ void __launch_bounds__(256) k_agg2(const float* __restrict__ b2,
                                              float* __restrict__ out) {
    __shared__ int   ss[8 * 32];
    __shared__ float sp[8 * 32];
    int tid = threadIdx.x;
    int w = tid >> 5, l = tid & 31;
    int n = blockIdx.x * 8 + w;
    if (n >= NN) return;
    int start = g_rowptr[n], end = g_rowptr[n + 1];
    float ad = g_ald2[n];
    int g = l >> 3, q = l & 7;
    float z = 0.f;
    float4 acc = make_float4(0.f, 0.f, 0.f, 0.f);
    for (int base = start; base < end; base += 32) {
        int j = base + l;
        float p = 0.f;
        int s = 0;
        if (j < end) {
            int2 cs = g_csr[j];
            s = cs.x;
            float v = g_als2[cs.x] + ad + g_ale2[cs.y];
            v = (v > 0.f) ? v : 0.2f * v;
            p = __expf(v);
            z += p;
            g_e2[cs.y] = p;                 // unnormalized; rescaled in k_tail
        }
        ss[w * 32 + l] = s;
        sp[w * 32 + l] = p;
        __syncwarp();
        int cnt = min(32, end - base);
        for (int t4 = 0; t4 < cnt; t4 += 4) {
            int t = t4 + g;
            if (t < cnt) {
                int sv = ss[w * 32 + t];
                float pw = sp[w * 32 + t];
                float4 hv = ((const float4*)g_h2lin)[(long long)sv * 8 + q];
                acc.x += pw * hv.x; acc.y += pw * hv.y;
                acc.z += pw * hv.z; acc.w += pw * hv.w;
            }
        }
        __syncwarp();
    }
    #pragma unroll
    for (int o = 16; o > 0; o >>= 1) z += __shfl_xor_sync(0xffffffffu, z, o);
    acc.x += __shfl_xor_sync(0xffffffffu, acc.x, 8);
    acc.y += __shfl_xor_sync(0xffffffffu, acc.y, 8);
    acc.z += __shfl_xor_sync(0xffffffffu, acc.z, 8);
    acc.w += __shfl_xor_sync(0xffffffffu, acc.w, 8);
    acc.x += __shfl_xor_sync(0xffffffffu, acc.x, 16);
    acc.y += __shfl_xor_sync(0xffffffffu, acc.y, 16);
    acc.z += __shfl_xor_sync(0xffffffffu, acc.z, 16);
    acc.w += __shfl_xor_sync(0xffffffffu, acc.w, 16);
    if (l == 0) g_z2[n] = z;
    if (l < 8) {
        float inv = 1.f / z;
        float4 bb = ((const float4*)b2)[q];
        float4 o4;
        o4.x = acc.x * inv + bb.x; o4.x = (o4.x > 0.f) ? o4.x : (__expf(o4.x) - 1.f);
        o4.y = acc.y * inv + bb.y; o4.y = (o4.y > 0.f) ? o4.y : (__expf(o4.y) - 1.f);
        o4.z = acc.z * inv + bb.z; o4.z = (o4.z > 0.f) ? o4.z : (__expf(o4.z) - 1.f);
        o4.w = acc.w * inv + bb.w; o4.w = (o4.w > 0.f) ? o4.w : (__expf(o4.w) - 1.f);
        ((float4*)out)[(long long)n * 8 + q] = o4;
    }
}

// edge_index (as float) + normalized alpha outputs
__global__ void k_tail(const int* __restrict__ ei, float* __restrict__ out,
                       int has_idx, int has_alpha) {
    int e = blockIdx.x * blockDim.x + threadIdx.x;
    if (e >= EP) return;
    int s, d;
    if (e < EE) { s = ei[e]; d = ei[EE + e]; } else { s = d = e - EE; }
    if (has_idx) {
        out[(long long)NN * CC + e] = (float)s;
        out[(long long)NN * CC + EP + e] = (float)d;
    }
    if (has_alpha) out[(long long)NN * CC + 2LL * EP + e] = g_e2[e] / g_z2[d];
}

extern "C" void kernel_launch(void* const* d_in, const int* in_sizes, int n_in,
                              void* d_out, int out_size) {
    const float* x    = (const float*)d_in[0];
    const int*   ei   = (const int*)d_in[1];
    const float* ea   = (const float*)d_in[2];
    const float* W1   = (const float*)d_in[3];
    const float* W1e  = (const float*)d_in[4];
    const float* a1s  = (const float*)d_in[5];
    const float* a1d  = (const float*)d_in[6];
    const float* a1e  = (const float*)d_in[7];
    const float* b1   = (const float*)d_in[8];
    const float* W2   = (const float*)d_in[9];
    const float* W2e  = (const float*)d_in[10];
    const float* a2s  = (const float*)d_in[11];
    const float* a2d  = (const float*)d_in[12];
    const float* a2e  = (const float*)d_in[13];
    const float* b2   = (const float*)d_in[14];
    float* out = (float*)d_out;

    int has_idx   = (out_size >= NN * CC + 2 * EP) ? 1 : 0;
    int has_alpha = (out_size >= NN * CC + 2 * EP + EP) ? 1 : 0;

    k_init<<<512, 256>>>();
    k_v<<<1, 96>>>(W1e, a1e, W2e, a2e);
    k_fused1<<<GEMM_BLOCKS + DEG_BLOCKS, 256>>>(x, W1, a1s, a1d, ei, ea);
    k_ale_self<<<(NN + 255) / 256, 256>>>();
    k_scan1<<<NB_SCAN, SCAN_B>>>();
    k_scan2<<<1, 256>>>();
    k_scan3<<<(NN + 255) / 256, 256>>>();
    k_fill<<<(EP + 255) / 256, 256>>>(ei);
    k_agg1<<<(NN + 7) / 8, 256>>>();
    k_node2<<<(NN + 31) / 32, 256>>>(b1, W2, a2s, a2d);
    k_agg2<<<(NN + 7) / 8, 256>>>(b2, out);
    k_tail<<<(EP + 255) / 256, 256>>>(ei, out, has_idx, has_alpha);
}

// round 14
// speedup vs baseline: 1.1963x; 1.0893x over previous
#include <cuda_runtime.h>
#include <cuda_fp16.h>
#include <math.h>

#define NN 100000
#define EE 1600000
#define EP 1700000      // EE + NN (with self loops)
#define IND 128
#define HH 4
#define CC 32
#define HC 128          // HH*CC
#define ED 16
#define SCAN_B 512
#define NB_SCAN ((NN + SCAN_B - 1) / SCAN_B)   // 196
#define GEMM_BLOCKS ((NN + 63) / 64)           // 1563
#define DEG_BLOCKS ((EE + 255) / 256)          // 6250

// ---------------- scratch ----------------
__device__ float  g_alacc[NN * HH];   // per-dst sum of edge head-dots (layer 1)
__device__ float2 g_svd[NN];          // per-dst (sum of layer-2 edge dots, degree)
__device__ float g_ale1[EP * HH];
__device__ float g_ale2[EP];
__device__ __half g_h1h[NN * HC];     // fp16 payload for layer-1 gather
__device__ float g_als1[NN * HH];
__device__ float g_ald1[NN * HH];
__device__ float g_out1[NN * HC];
__device__ float g_h2lin[NN * CC];
__device__ float g_als2[NN];
__device__ float g_ald2[NN];
__device__ float g_z2[NN];
__device__ float g_e2[EP];           // unnormalized p for layer 2 (for alpha output)
__device__ float g_v1[ED * HH];
__device__ float g_v2[ED];
// CSR
__device__ int  g_rowptr[NN + 1];
__device__ int  g_cursor[NN];
__device__ int  g_bsum[NB_SCAN];
__device__ int  g_boff[NB_SCAN];
__device__ int2 g_csr[EP];           // (src, edge_id) per slot, grouped by dst

__device__ __forceinline__ void red4(float* addr, float4 v) {
    asm volatile("red.global.add.v4.f32 [%0], {%1,%2,%3,%4};"
                 :: "l"(addr), "f"(v.x), "f"(v.y), "f"(v.z), "f"(v.w) : "memory");
}
__device__ __forceinline__ void red2(float2* addr, float2 v) {
    asm volatile("red.global.add.v2.f32 [%0], {%1,%2};"
                 :: "l"(addr), "f"(v.x), "f"(v.y) : "memory");
}

// ---------------- setup kernels ----------------
__global__ void k_init() {
    int i = blockIdx.x * blockDim.x + threadIdx.x;
    int stride = gridDim.x * blockDim.x;
    float4 z4 = make_float4(0.f, 0.f, 0.f, 0.f);
    for (int j = i; j < NN; j += stride) {
        ((float4*)g_alacc)[j] = z4;
        g_svd[j] = make_float2(0.f, 0.f);
    }
}

__global__ void k_v(const float* __restrict__ W1e, const float* __restrict__ a1e,
                    const float* __restrict__ W2e, const float* __restrict__ a2e) {
    int t = threadIdx.x;
    if (t < ED * HH) {
        int d = t / HH, h = t % HH;
        float s = 0.f;
        #pragma unroll
        for (int c = 0; c < CC; c++) s += W1e[d * HC + h * CC + c] * a1e[h * CC + c];
        g_v1[d * HH + h] = s;
    } else if (t < ED * HH + ED) {
        int d = t - ED * HH;
        float s = 0.f;
        #pragma unroll
        for (int c = 0; c < CC; c++) s += W2e[d * CC + c] * a2e[c];
        g_v2[d] = s;
    }
}

// ---------------- fused phase 1: gemm1 (FMA-bound) + degale (mem/atomic-bound) ----
// Interleaved block mapping: blockIdx % 5 == 0 -> gemm block (1563), else degale (6250).
__global__ void __launch_bounds__(256) k_fused1(
        const float* __restrict__ x, const float* __restrict__ W1,
        const float* __restrict__ a1s, const float* __restrict__ a1d,
        const int* __restrict__ ei, const float* __restrict__ ea) {
    __shared__ float xs[64 * IND];       // 32 KB (gemm branch only)
    int bid = blockIdx.x;
    int tid = threadIdx.x;
    if ((bid % 5) == 0 && (bid / 5) < GEMM_BLOCKS) {
        // ---- gemm1: 64 nodes/block, 8 nodes/warp, lane = 4 output cols ----
        int gb = bid / 5;
        int w = tid >> 5, l = tid & 31;
        int base = gb * 64;
        const float4* xv4 = (const float4*)x;
        #pragma unroll
        for (int i = 0; i < 8; i++) {
            int j = tid + i * 256;
            long long gi = (long long)base * 32 + j;
            ((float4*)xs)[j] = (gi < (long long)NN * 32) ? xv4[gi] : make_float4(0.f,0.f,0.f,0.f);
        }
        __syncthreads();
        float4 acc[8];
        #pragma unroll
        for (int i = 0; i < 8; i++) acc[i] = make_float4(0.f,0.f,0.f,0.f);
        const float4* W1v = (const float4*)W1;
        #pragma unroll 2
        for (int k4 = 0; k4 < 32; k4++) {
            float4 w0 = W1v[(k4 * 4 + 0) * 32 + l];
            float4 w1 = W1v[(k4 * 4 + 1) * 32 + l];
            float4 w2 = W1v[(k4 * 4 + 2) * 32 + l];
            float4 w3 = W1v[(k4 * 4 + 3) * 32 + l];
            #pragma unroll
            for (int i = 0; i < 8; i++) {
                float4 xv = ((const float4*)xs)[(w * 8 + i) * 32 + k4];
                acc[i].x += xv.x * w0.x + xv.y * w1.x + xv.z * w2.x + xv.w * w3.x;
                acc[i].y += xv.x * w0.y + xv.y * w1.y + xv.z * w2.y + xv.w * w3.y;
                acc[i].z += xv.x * w0.z + xv.y * w1.z + xv.z * w2.z + xv.w * w3.z;
                acc[i].w += xv.x * w0.w + xv.y * w1.w + xv.z * w2.w + xv.w * w3.w;
            }
        }
        float4 as = ((const float4*)a1s)[l];
        float4 ad = ((const float4*)a1d)[l];
        #pragma unroll
        for (int i = 0; i < 8; i++) {
            int n = base + w * 8 + i;
            if (n >= NN) break;
            __half2 h0 = __floats2half2_rn(acc[i].x, acc[i].y);
            __half2 h1 = __floats2half2_rn(acc[i].z, acc[i].w);
            uint2 u;
            u.x = *reinterpret_cast<unsigned*>(&h0);
            u.y = *reinterpret_cast<unsigned*>(&h1);
            ((uint2*)g_h1h)[(long long)n * 32 + l] = u;
            float ps = acc[i].x * as.x + acc[i].y * as.y + acc[i].z * as.z + acc[i].w * as.w;
            float pd = acc[i].x * ad.x + acc[i].y * ad.y + acc[i].z * ad.z + acc[i].w * ad.w;
            #pragma unroll
            for (int o = 4; o > 0; o >>= 1) {
                ps += __shfl_down_sync(0xffffffffu, ps, o);
                pd += __shfl_down_sync(0xffffffffu, pd, o);
            }
            if ((l & 7) == 0) {
                g_als1[n * HH + (l >> 3)] = ps;
                g_ald1[n * HH + (l >> 3)] = pd;
            }
        }
    } else {
        // ---- degale: per real edge, edge dots; accumulate the DOTS per dst
        //      (linearity: dot(mean_attr,v) = (sum_e dot(attr_e,v)) / deg)
        int db = bid - bid / 5 - 1;               // 0..6249
        int e = db * 256 + tid;
        if (e >= EE) return;
        int d = ei[EE + e];
        const float4* av4 = (const float4*)(ea + (long long)e * ED);
        float4 a0 = av4[0], a1 = av4[1], a2 = av4[2], a3 = av4[3];
        float a[ED] = {a0.x,a0.y,a0.z,a0.w, a1.x,a1.y,a1.z,a1.w,
                       a2.x,a2.y,a2.z,a2.w, a3.x,a3.y,a3.z,a3.w};
        float s0 = 0.f, s1 = 0.f, s2 = 0.f, s3 = 0.f, sv = 0.f;
        #pragma unroll
        for (int k = 0; k < ED; k++) {
            float av = a[k];
            s0 += av * g_v1[k * HH + 0];
            s1 += av * g_v1[k * HH + 1];
            s2 += av * g_v1[k * HH + 2];
            s3 += av * g_v1[k * HH + 3];
            sv += av * g_v2[k];
        }
        float4 s4 = make_float4(s0, s1, s2, s3);
        ((float4*)g_ale1)[e] = s4;
        g_ale2[e] = sv;
        red4(&g_alacc[d * HH], s4);
        red2(&g_svd[d], make_float2(sv, 1.f));
    }
}

// self-loop edge dots from accumulated per-dst dot sums
__global__ void k_ale_self() {
    int n = blockIdx.x * blockDim.x + threadIdx.x;
    if (n >= NN) return;
    float2 svd = g_svd[n];
    float invd = 1.f / fmaxf(svd.y, 1.f);
    float4 s = ((const float4*)g_alacc)[n];
    ((float4*)g_ale1)[EE + n] = make_float4(s.x * invd, s.y * invd, s.z * invd, s.w * invd);
    g_ale2[EE + n] = svd.x * invd;
}

// ---------------- CSR build ----------------
__global__ void k_scan1() {
    __shared__ int sh[SCAN_B];
    int tid = threadIdx.x;
    int n = blockIdx.x * SCAN_B + tid;
    int c = (n < NN) ? ((int)g_svd[n].y + 1) : 0;   // +1 self loop
    sh[tid] = c;
    __syncthreads();
    #pragma unroll
    for (int o = 1; o < SCAN_B; o <<= 1) {
        int v = (tid >= o) ? sh[tid - o] : 0;
        __syncthreads();
        sh[tid] += v;
        __syncthreads();
    }
    if (n < NN) g_rowptr[n] = sh[tid] - c;        // exclusive
    if (tid == SCAN_B - 1) g_bsum[blockIdx.x] = sh[tid];
}

__global__ void k_scan2() {
    __shared__ int sh[256];
    int tid = threadIdx.x;
    int c = (tid < NB_SCAN) ? g_bsum[tid] : 0;
    sh[tid] = c;
    __syncthreads();
    #pragma unroll
    for (int o = 1; o < 256; o <<= 1) {
        int v = (tid >= o) ? sh[tid - o] : 0;
        __syncthreads();
        sh[tid] += v;
        __syncthreads();
    }
    if (tid < NB_SCAN) g_boff[tid] = sh[tid] - c; // exclusive
}

__global__ void k_scan3() {
    int n = blockIdx.x * blockDim.x + threadIdx.x;
    if (n < NN) {
        int rp = g_rowptr[n] + g_boff[n / SCAN_B];
        g_rowptr[n] = rp;
        g_cursor[n] = rp;                          // fill's atomic cursor starts at row base
    }
    if (n == 0) g_rowptr[NN] = EP;
}

__global__ void k_fill(const int* __restrict__ ei) {
    int e = blockIdx.x * blockDim.x + threadIdx.x;
    if (e >= EP) return;
    int s, d;
    if (e < EE) { s = ei[e]; d = ei[EE + e]; } else { s = d = e - EE; }
    int slot = atomicAdd(&g_cursor[d], 1);
    g_csr[slot] = make_int2(s, e);
}

// ---------------- layer 1 aggregation ----------------
// fused softmax + aggregation, warp per dst node (atomic-free); fp16 payload gather
__global__ void __launch_bounds__(256) k_agg1() {
    __shared__ int   ss[8 * 32];
    __shared__ float sp[8 * 32 * 4];
    int tid = threadIdx.x;
    int w = tid >> 5, l = tid & 31;
    int n = blockIdx.x * 8 + w;
    if (n >= NN) return;
    int start = g_rowptr[n], end = g_rowptr[n + 1];
    float4 ad = ((const float4*)g_ald1)[n];
    int h = l >> 3;
    float4 z = make_float4(0.f, 0.f, 0.f, 0.f);
    float4 acc = make_float4(0.f, 0.f, 0.f, 0.f);
    for (int base = start; base < end; base += 32) {
        int j = base + l;
        float4 p = make_float4(0.f, 0.f, 0.f, 0.f);
        int s = 0;
        if (j < end) {
            int2 cs = g_csr[j];
            s = cs.x;
            float4 as = ((const float4*)g_als1)[cs.x];
            float4 ae = ((const float4*)g_ale1)[cs.y];
            float v;
            v = as.x + ad.x + ae.x; v = (v > 0.f) ? v : 0.2f * v; p.x = __expf(v);
            v = as.y + ad.y + ae.y; v = (v > 0.f) ? v : 0.2f * v; p.y = __expf(v);
            v = as.z + ad.z + ae.z; v = (v > 0.f) ? v : 0.2f * v; p.z = __expf(v);
            v = as.w + ad.w + ae.w; v = (v > 0.f) ? v : 0.2f * v; p.w = __expf(v);
            z.x += p.x; z.y += p.y; z.z += p.z; z.w += p.w;
        }
        ss[w * 32 + l] = s;
        ((float4*)sp)[w * 32 + l] = p;
        __syncwarp();
        int cnt = min(32, end - base);
        #pragma unroll 4
        for (int t = 0; t < cnt; t++) {
            int sv = ss[w * 32 + t];
            float pw = sp[(w * 32 + t) * 4 + h];
            uint2 u = ((const uint2*)g_h1h)[(long long)sv * 32 + l];
            __half2 h0 = *reinterpret_cast<__half2*>(&u.x);
            __half2 h1 = *reinterpret_cast<__half2*>(&u.y);
            float2 f0 = __half22float2(h0);
            float2 f1 = __half22float2(h1);
            acc.x += pw * f0.x; acc.y += pw * f0.y;
            acc.z += pw * f1.x; acc.w += pw * f1.y;
        }
        __syncwarp();
    }
    #pragma unroll
    for (int o = 16; o > 0; o >>= 1) {
        z.x += __shfl_xor_sync(0xffffffffu, z.x, o);
        z.y += __shfl_xor_sync(0xffffffffu, z.y, o);
        z.z += __shfl_xor_sync(0xffffffffu, z.z, o);
        z.w += __shfl_xor_sync(0xffffffffu, z.w, o);
    }
    float zh = (h == 0) ? z.x : (h == 1) ? z.y : (h == 2) ? z.z : z.w;
    float inv = 1.f / zh;
    acc.x *= inv; acc.y *= inv; acc.z *= inv; acc.w *= inv;
    ((float4*)g_out1)[(long long)n * 32 + l] = acc;
}

// ---------------- layer 2 ----------------
// 64 nodes/block, 8 nodes/warp: ELU epilogue + 128x32 GEMV + logits
__global__ void __launch_bounds__(256) k_node2(
        const float* __restrict__ b1, const float* __restrict__ W2,
        const float* __restrict__ a2s, const float* __restrict__ a2d) {
    __shared__ float hs[64 * HC];        // 32 KB
    int tid = threadIdx.x;
    int w = tid >> 5, l = tid & 31;
    int base = blockIdx.x * 64;
    #pragma unroll
    for (int i = 0; i < 8; i++) {
        int j = tid + i * 256;
        long long gi = (long long)base * 32 + j;
        float4 v = (gi < (long long)NN * 32) ? ((const float4*)g_out1)[gi]
                                             : make_float4(0.f,0.f,0.f,0.f);
        float4 bb = ((const float4*)b1)[j & 31];
        v.x += bb.x; v.y += bb.y; v.z += bb.z; v.w += bb.w;
        v.x = (v.x > 0.f) ? v.x : (__expf(v.x) - 1.f);
        v.y = (v.y > 0.f) ? v.y : (__expf(v.y) - 1.f);
        v.z = (v.z > 0.f) ? v.z : (__expf(v.z) - 1.f);
        v.w = (v.w > 0.f) ? v.w : (__expf(v.w) - 1.f);
        ((float4*)hs)[j] = v;
    }
    __syncthreads();
    float acc[8] = {0.f, 0.f, 0.f, 0.f, 0.f, 0.f, 0.f, 0.f};
    #pragma unroll 4
    for (int k4 = 0; k4 < 32; k4++) {
        float w0 = W2[(k4 * 4 + 0) * 32 + l];
        float w1 = W2[(k4 * 4 + 1) * 32 + l];
        float w2v = W2[(k4 * 4 + 2) * 32 + l];
        float w3 = W2[(k4 * 4 + 3) * 32 + l];
        #pragma unroll
        for (int i = 0; i < 8; i++) {
            float4 xv = ((const float4*)hs)[(w * 8 + i) * 32 + k4];
            acc[i] += xv.x * w0 + xv.y * w1 + xv.z * w2v + xv.w * w3;
        }
    }
    float cs = a2s[l], cd = a2d[l];
    #pragma unroll
    for (int i = 0; i < 8; i++) {
        int n = base + w * 8 + i;
        if (n >= NN) break;
        float a = acc[i];
        g_h2lin[(long long)n * CC + l] = a;
        float ps = a * cs;
        float pd = a * cd;
        #pragma unroll
        for (int o = 16; o > 0; o >>= 1) {
            ps += __shfl_down_sync(0xffffffffu, ps, o);
            pd += __shfl_down_sync(0xffffffffu, pd, o);
        }
        if (l == 0) { g_als2[n] = ps; g_ald2[n] = pd; }
    }
}

// fused softmax + aggregation + bias + ELU, warp per dst node; 8-lane edge groups
__global__ void __launch_bounds__(256) k_agg2(const float* __restrict__ b2,
                                              float* __restrict__ out) {
    __shared__ int   ss[8 * 32];
    __shared__ float sp[8 * 32];
    int tid = threadIdx.x;
    int w = tid >> 5, l = tid & 31;
    int n = blockIdx.x * 8 + w;
    if (n >= NN) return;
    int start = g_rowptr[n], end = g_rowptr[n + 1];
    float ad = g_ald2[n];
    int g = l >> 3, q = l & 7;
    float z = 0.f;
    float4 acc = make_float4(0.f, 0.f, 0.f, 0.f);
    for (int base = start; base < end; base += 32) {
        int j = base + l;
        float p = 0.f;
        int s = 0;
        if (j < end) {
            int2 cs = g_csr[j];
            s = cs.x;
            float v = g_als2[cs.x] + ad + g_ale2[cs.y];
            v = (v > 0.f) ? v : 0.2f * v;
            p = __expf(v);
            z += p;
            g_e2[cs.y] = p;                 // unnormalized; rescaled in k_tail
        }
        ss[w * 32 + l] = s;
        sp[w * 32 + l] = p;
        __syncwarp();
        int cnt = min(32, end - base);
        for (int t4 = 0; t4 < cnt; t4 += 4) {
            int t = t4 + g;
            if (t < cnt) {
                int sv = ss[w * 32 + t];
                float pw = sp[w * 32 + t];
                float4 hv = ((const float4*)g_h2lin)[(long long)sv * 8 + q];
                acc.x += pw * hv.x; acc.y += pw * hv.y;
                acc.z += pw * hv.z; acc.w += pw * hv.w;
            }
        }
        __syncwarp();
    }
    #pragma unroll
    for (int o = 16; o > 0; o >>= 1) z += __shfl_xor_sync(0xffffffffu, z, o);
    acc.x += __shfl_xor_sync(0xffffffffu, acc.x, 8);
    acc.y += __shfl_xor_sync(0xffffffffu, acc.y, 8);
    acc.z += __shfl_xor_sync(0xffffffffu, acc.z, 8);
    acc.w += __shfl_xor_sync(0xffffffffu, acc.w, 8);
    acc.x += __shfl_xor_sync(0xffffffffu, acc.x, 16);
    acc.y += __shfl_xor_sync(0xffffffffu, acc.y, 16);
    acc.z += __shfl_xor_sync(0xffffffffu, acc.z, 16);
    acc.w += __shfl_xor_sync(0xffffffffu, acc.w, 16);
    if (l == 0) g_z2[n] = z;
    if (l < 8) {
        float inv = 1.f / z;
        float4 bb = ((const float4*)b2)[q];
        float4 o4;
        o4.x = acc.x * inv + bb.x; o4.x = (o4.x > 0.f) ? o4.x : (__expf(o4.x) - 1.f);
        o4.y = acc.y * inv + bb.y; o4.y = (o4.y > 0.f) ? o4.y : (__expf(o4.y) - 1.f);
        o4.z = acc.z * inv + bb.z; o4.z = (o4.z > 0.f) ? o4.z : (__expf(o4.z) - 1.f);
        o4.w = acc.w * inv + bb.w; o4.w = (o4.w > 0.f) ? o4.w : (__expf(o4.w) - 1.f);
        ((float4*)out)[(long long)n * 8 + q] = o4;
    }
}

// edge_index (as float) + normalized alpha outputs
__global__ void k_tail(const int* __restrict__ ei, float* __restrict__ out,
                       int has_idx, int has_alpha) {
    int e = blockIdx.x * blockDim.x + threadIdx.x;
    if (e >= EP) return;
    int s, d;
    if (e < EE) { s = ei[e]; d = ei[EE + e]; } else { s = d = e - EE; }
    if (has_idx) {
        out[(long long)NN * CC + e] = (float)s;
        out[(long long)NN * CC + EP + e] = (float)d;
    }
    if (has_alpha) out[(long long)NN * CC + 2LL * EP + e] = g_e2[e] / g_z2[d];
}

extern "C" void kernel_launch(void* const* d_in, const int* in_sizes, int n_in,
                              void* d_out, int out_size) {
    const float* x    = (const float*)d_in[0];
    const int*   ei   = (const int*)d_in[1];
    const float* ea   = (const float*)d_in[2];
    const float* W1   = (const float*)d_in[3];
    const float* W1e  = (const float*)d_in[4];
    const float* a1s  = (const float*)d_in[5];
    const float* a1d  = (const float*)d_in[6];
    const float* a1e  = (const float*)d_in[7];
    const float* b1   = (const float*)d_in[8];
    const float* W2   = (const float*)d_in[9];
    const float* W2e  = (const float*)d_in[10];
    const float* a2s  = (const float*)d_in[11];
    const float* a2d  = (const float*)d_in[12];
    const float* a2e  = (const float*)d_in[13];
    const float* b2   = (const float*)d_in[14];
    float* out = (float*)d_out;

    int has_idx   = (out_size >= NN * CC + 2 * EP) ? 1 : 0;
    int has_alpha = (out_size >= NN * CC + 2 * EP + EP) ? 1 : 0;

    k_init<<<512, 256>>>();
    k_v<<<1, 96>>>(W1e, a1e, W2e, a2e);
    k_fused1<<<GEMM_BLOCKS + DEG_BLOCKS, 256>>>(x, W1, a1s, a1d, ei, ea);
    k_ale_self<<<(NN + 255) / 256, 256>>>();
    k_scan1<<<NB_SCAN, SCAN_B>>>();
    k_scan2<<<1, 256>>>();
    k_scan3<<<(NN + 255) / 256, 256>>>();
    k_fill<<<(EP + 255) / 256, 256>>>(ei);
    k_agg1<<<(NN + 7) / 8, 256>>>();
    k_node2<<<(NN + 63) / 64, 256>>>(b1, W2, a2s, a2d);
    k_agg2<<<(NN + 7) / 8, 256>>>(b2, out);
    k_tail<<<(EP + 255) / 256, 256>>>(ei, out, has_idx, has_alpha);
}

// round 15
// speedup vs baseline: 1.2256x; 1.0245x over previous
#include <cuda_runtime.h>
#include <cuda_fp16.h>
#include <math.h>

#define NN 100000
#define EE 1600000
#define EP 1700000      // EE + NN (with self loops)
#define IND 128
#define HH 4
#define CC 32
#define HC 128          // HH*CC
#define ED 16
#define SCAN_B 512
#define NB_SCAN ((NN + SCAN_B - 1) / SCAN_B)   // 196
#define GEMM_BLOCKS ((NN + 63) / 64)           // 1563
#define DEG_BLOCKS ((EE + 255) / 256)          // 6250

// ---------------- scratch ----------------
__device__ float  g_alacc[NN * HH];   // per-dst sum of edge head-dots (layer 1)
__device__ float2 g_svd[NN];          // per-dst (sum of layer-2 edge dots, degree)
__device__ float g_ale1[EP * HH];
__device__ float g_ale2[EP];
__device__ __half g_h1h[NN * HC];     // fp16 payload for layer-1 gather
__device__ float g_als1[NN * HH];
__device__ float g_ald1[NN * HH];
__device__ __half g_o1h[NN * HC];     // fp16 layer-1 output (agg1 -> node2)
__device__ __half g_h2h[NN * CC];     // fp16 payload for layer-2 gather
__device__ float g_als2[NN];
__device__ float g_ald2[NN];
__device__ float g_z2[NN];
__device__ float g_e2[EP];           // unnormalized p for layer 2 (for alpha output)
__device__ float g_v1[ED * HH];
__device__ float g_v2[ED];
// CSR
__device__ int  g_rowptr[NN + 1];
__device__ int  g_cursor[NN];
__device__ int  g_bsum[NB_SCAN];
__device__ int  g_boff[NB_SCAN];
__device__ int2 g_csr[EP];           // (src, edge_id) per slot, grouped by dst

__device__ __forceinline__ void red4(float* addr, float4 v) {
    asm volatile("red.global.add.v4.f32 [%0], {%1,%2,%3,%4};"
                 :: "l"(addr), "f"(v.x), "f"(v.y), "f"(v.z), "f"(v.w) : "memory");
}
__device__ __forceinline__ void red2(float2* addr, float2 v) {
    asm volatile("red.global.add.v2.f32 [%0], {%1,%2};"
                 :: "l"(addr), "f"(v.x), "f"(v.y) : "memory");
}
__device__ __forceinline__ uint2 pack4h(float a, float b, float c, float d) {
    __half2 h0 = __floats2half2_rn(a, b);
    __half2 h1 = __floats2half2_rn(c, d);
    uint2 u;
    u.x = *reinterpret_cast<unsigned*>(&h0);
    u.y = *reinterpret_cast<unsigned*>(&h1);
    return u;
}
__device__ __forceinline__ float4 unpack4h(uint2 u) {
    __half2 h0 = *reinterpret_cast<__half2*>(&u.x);
    __half2 h1 = *reinterpret_cast<__half2*>(&u.y);
    float2 f0 = __half22float2(h0);
    float2 f1 = __half22float2(h1);
    return make_float4(f0.x, f0.y, f1.x, f1.y);
}

// ---------------- setup kernels ----------------
__global__ void k_init() {
    int i = blockIdx.x * blockDim.x + threadIdx.x;
    int stride = gridDim.x * blockDim.x;
    float4 z4 = make_float4(0.f, 0.f, 0.f, 0.f);
    for (int j = i; j < NN; j += stride) {
        ((float4*)g_alacc)[j] = z4;
        g_svd[j] = make_float2(0.f, 0.f);
    }
}

__global__ void k_v(const float* __restrict__ W1e, const float* __restrict__ a1e,
                    const float* __restrict__ W2e, const float* __restrict__ a2e) {
    int t = threadIdx.x;
    if (t < ED * HH) {
        int d = t / HH, h = t % HH;
        float s = 0.f;
        #pragma unroll
        for (int c = 0; c < CC; c++) s += W1e[d * HC + h * CC + c] * a1e[h * CC + c];
        g_v1[d * HH + h] = s;
    } else if (t < ED * HH + ED) {
        int d = t - ED * HH;
        float s = 0.f;
        #pragma unroll
        for (int c = 0; c < CC; c++) s += W2e[d * CC + c] * a2e[c];
        g_v2[d] = s;
    }
}

// ---------------- fused phase 1: gemm1 (FMA-bound) + degale (mem/atomic-bound) ----
// Interleaved block mapping: blockIdx % 5 == 0 -> gemm block (1563), else degale (6250).
__global__ void __launch_bounds__(256) k_fused1(
        const float* __restrict__ x, const float* __restrict__ W1,
        const float* __restrict__ a1s, const float* __restrict__ a1d,
        const int* __restrict__ ei, const float* __restrict__ ea) {
    __shared__ float xs[64 * IND];       // 32 KB (gemm branch only)
    int bid = blockIdx.x;
    int tid = threadIdx.x;
    if ((bid % 5) == 0 && (bid / 5) < GEMM_BLOCKS) {
        // ---- gemm1: 64 nodes/block, 8 nodes/warp, lane = 4 output cols ----
        int gb = bid / 5;
        int w = tid >> 5, l = tid & 31;
        int base = gb * 64;
        const float4* xv4 = (const float4*)x;
        #pragma unroll
        for (int i = 0; i < 8; i++) {
            int j = tid + i * 256;
            long long gi = (long long)base * 32 + j;
            ((float4*)xs)[j] = (gi < (long long)NN * 32) ? xv4[gi] : make_float4(0.f,0.f,0.f,0.f);
        }
        __syncthreads();
        float4 acc[8];
        #pragma unroll
        for (int i = 0; i < 8; i++) acc[i] = make_float4(0.f,0.f,0.f,0.f);
        const float4* W1v = (const float4*)W1;
        #pragma unroll 2
        for (int k4 = 0; k4 < 32; k4++) {
            float4 w0 = W1v[(k4 * 4 + 0) * 32 + l];
            float4 w1 = W1v[(k4 * 4 + 1) * 32 + l];
            float4 w2 = W1v[(k4 * 4 + 2) * 32 + l];
            float4 w3 = W1v[(k4 * 4 + 3) * 32 + l];
            #pragma unroll
            for (int i = 0; i < 8; i++) {
                float4 xv = ((const float4*)xs)[(w * 8 + i) * 32 + k4];
                acc[i].x += xv.x * w0.x + xv.y * w1.x + xv.z * w2.x + xv.w * w3.x;
                acc[i].y += xv.x * w0.y + xv.y * w1.y + xv.z * w2.y + xv.w * w3.y;
                acc[i].z += xv.x * w0.z + xv.y * w1.z + xv.z * w2.z + xv.w * w3.z;
                acc[i].w += xv.x * w0.w + xv.y * w1.w + xv.z * w2.w + xv.w * w3.w;
            }
        }
        float4 as = ((const float4*)a1s)[l];
        float4 ad = ((const float4*)a1d)[l];
        #pragma unroll
        for (int i = 0; i < 8; i++) {
            int n = base + w * 8 + i;
            if (n >= NN) break;
            ((uint2*)g_h1h)[(long long)n * 32 + l] =
                pack4h(acc[i].x, acc[i].y, acc[i].z, acc[i].w);
            float ps = acc[i].x * as.x + acc[i].y * as.y + acc[i].z * as.z + acc[i].w * as.w;
            float pd = acc[i].x * ad.x + acc[i].y * ad.y + acc[i].z * ad.z + acc[i].w * ad.w;
            #pragma unroll
            for (int o = 4; o > 0; o >>= 1) {
                ps += __shfl_down_sync(0xffffffffu, ps, o);
                pd += __shfl_down_sync(0xffffffffu, pd, o);
            }
            if ((l & 7) == 0) {
                g_als1[n * HH + (l >> 3)] = ps;
                g_ald1[n * HH + (l >> 3)] = pd;
            }
        }
    } else {
        // ---- degale: per real edge, edge dots; accumulate the DOTS per dst
        //      (linearity: dot(mean_attr,v) = (sum_e dot(attr_e,v)) / deg)
        int db = bid - bid / 5 - 1;               // 0..6249
        int e = db * 256 + tid;
        if (e >= EE) return;
        int d = ei[EE + e];
        const float4* av4 = (const float4*)(ea + (long long)e * ED);
        float4 a0 = av4[0], a1 = av4[1], a2 = av4[2], a3 = av4[3];
        float a[ED] = {a0.x,a0.y,a0.z,a0.w, a1.x,a1.y,a1.z,a1.w,
                       a2.x,a2.y,a2.z,a2.w, a3.x,a3.y,a3.z,a3.w};
        float s0 = 0.f, s1 = 0.f, s2 = 0.f, s3 = 0.f, sv = 0.f;
        #pragma unroll
        for (int k = 0; k < ED; k++) {
            float av = a[k];
            s0 += av * g_v1[k * HH + 0];
            s1 += av * g_v1[k * HH + 1];
            s2 += av * g_v1[k * HH + 2];
            s3 += av * g_v1[k * HH + 3];
            sv += av * g_v2[k];
        }
        float4 s4 = make_float4(s0, s1, s2, s3);
        ((float4*)g_ale1)[e] = s4;
        g_ale2[e] = sv;
        red4(&g_alacc[d * HH], s4);
        red2(&g_svd[d], make_float2(sv, 1.f));
    }
}

// self-loop edge dots from accumulated per-dst dot sums
__global__ void k_ale_self() {
    int n = blockIdx.x * blockDim.x + threadIdx.x;
    if (n >= NN) return;
    float2 svd = g_svd[n];
    float invd = 1.f / fmaxf(svd.y, 1.f);
    float4 s = ((const float4*)g_alacc)[n];
    ((float4*)g_ale1)[EE + n] = make_float4(s.x * invd, s.y * invd, s.z * invd, s.w * invd);
    g_ale2[EE + n] = svd.x * invd;
}

// ---------------- CSR build ----------------
__global__ void k_scan1() {
    __shared__ int sh[SCAN_B];
    int tid = threadIdx.x;
    int n = blockIdx.x * SCAN_B + tid;
    int c = (n < NN) ? ((int)g_svd[n].y + 1) : 0;   // +1 self loop
    sh[tid] = c;
    __syncthreads();
    #pragma unroll
    for (int o = 1; o < SCAN_B; o <<= 1) {
        int v = (tid >= o) ? sh[tid - o] : 0;
        __syncthreads();
        sh[tid] += v;
        __syncthreads();
    }
    if (n < NN) g_rowptr[n] = sh[tid] - c;        // exclusive
    if (tid == SCAN_B - 1) g_bsum[blockIdx.x] = sh[tid];
}

__global__ void k_scan2() {
    __shared__ int sh[256];
    int tid = threadIdx.x;
    int c = (tid < NB_SCAN) ? g_bsum[tid] : 0;
    sh[tid] = c;
    __syncthreads();
    #pragma unroll
    for (int o = 1; o < 256; o <<= 1) {
        int v = (tid >= o) ? sh[tid - o] : 0;
        __syncthreads();
        sh[tid] += v;
        __syncthreads();
    }
    if (tid < NB_SCAN) g_boff[tid] = sh[tid] - c; // exclusive
}

__global__ void k_scan3() {
    int n = blockIdx.x * blockDim.x + threadIdx.x;
    if (n < NN) {
        int rp = g_rowptr[n] + g_boff[n / SCAN_B];
        g_rowptr[n] = rp;
        g_cursor[n] = rp;                          // fill's atomic cursor starts at row base
    }
    if (n == 0) g_rowptr[NN] = EP;
}

__global__ void k_fill(const int* __restrict__ ei) {
    int e = blockIdx.x * blockDim.x + threadIdx.x;
    if (e >= EP) return;
    int s, d;
    if (e < EE) { s = ei[e]; d = ei[EE + e]; } else { s = d = e - EE; }
    int slot = atomicAdd(&g_cursor[d], 1);
    g_csr[slot] = make_int2(s, e);
}

// ---------------- layer 1 aggregation ----------------
// fused softmax + aggregation, warp per dst node (atomic-free); fp16 payload gather
__global__ void __launch_bounds__(256) k_agg1() {
    __shared__ int   ss[8 * 32];
    __shared__ float sp[8 * 32 * 4];
    int tid = threadIdx.x;
    int w = tid >> 5, l = tid & 31;
    int n = blockIdx.x * 8 + w;
    if (n >= NN) return;
    int start = g_rowptr[n], end = g_rowptr[n + 1];
    float4 ad = ((const float4*)g_ald1)[n];
    int h = l >> 3;
    float4 z = make_float4(0.f, 0.f, 0.f, 0.f);
    float4 acc = make_float4(0.f, 0.f, 0.f, 0.f);
    for (int base = start; base < end; base += 32) {
        int j = base + l;
        float4 p = make_float4(0.f, 0.f, 0.f, 0.f);
        int s = 0;
        if (j < end) {
            int2 cs = g_csr[j];
            s = cs.x;
            float4 as = ((const float4*)g_als1)[cs.x];
            float4 ae = ((const float4*)g_ale1)[cs.y];
            float v;
            v = as.x + ad.x + ae.x; v = (v > 0.f) ? v : 0.2f * v; p.x = __expf(v);
            v = as.y + ad.y + ae.y; v = (v > 0.f) ? v : 0.2f * v; p.y = __expf(v);
            v = as.z + ad.z + ae.z; v = (v > 0.f) ? v : 0.2f * v; p.z = __expf(v);
            v = as.w + ad.w + ae.w; v = (v > 0.f) ? v : 0.2f * v; p.w = __expf(v);
            z.x += p.x; z.y += p.y; z.z += p.z; z.w += p.w;
        }
        ss[w * 32 + l] = s;
        ((float4*)sp)[w * 32 + l] = p;
        __syncwarp();
        int cnt = min(32, end - base);
        #pragma unroll 4
        for (int t = 0; t < cnt; t++) {
            int sv = ss[w * 32 + t];
            float pw = sp[(w * 32 + t) * 4 + h];
            float4 f = unpack4h(((const uint2*)g_h1h)[(long long)sv * 32 + l]);
            acc.x += pw * f.x; acc.y += pw * f.y;
            acc.z += pw * f.z; acc.w += pw * f.w;
        }
        __syncwarp();
    }
    #pragma unroll
    for (int o = 16; o > 0; o >>= 1) {
        z.x += __shfl_xor_sync(0xffffffffu, z.x, o);
        z.y += __shfl_xor_sync(0xffffffffu, z.y, o);
        z.z += __shfl_xor_sync(0xffffffffu, z.z, o);
        z.w += __shfl_xor_sync(0xffffffffu, z.w, o);
    }
    float zh = (h == 0) ? z.x : (h == 1) ? z.y : (h == 2) ? z.z : z.w;
    float inv = 1.f / zh;
    ((uint2*)g_o1h)[(long long)n * 32 + l] =
        pack4h(acc.x * inv, acc.y * inv, acc.z * inv, acc.w * inv);
}

// ---------------- layer 2 ----------------
// 64 nodes/block, 8 nodes/warp: ELU epilogue + 128x32 GEMV + logits
__global__ void __launch_bounds__(256) k_node2(
        const float* __restrict__ b1, const float* __restrict__ W2,
        const float* __restrict__ a2s, const float* __restrict__ a2d) {
    __shared__ float hs[64 * HC];        // 32 KB
    int tid = threadIdx.x;
    int w = tid >> 5, l = tid & 31;
    int base = blockIdx.x * 64;
    #pragma unroll
    for (int i = 0; i < 8; i++) {
        int j = tid + i * 256;
        long long gi = (long long)base * 32 + j;
        float4 v = (gi < (long long)NN * 32) ? unpack4h(((const uint2*)g_o1h)[gi])
                                             : make_float4(0.f,0.f,0.f,0.f);
        float4 bb = ((const float4*)b1)[j & 31];
        v.x += bb.x; v.y += bb.y; v.z += bb.z; v.w += bb.w;
        v.x = (v.x > 0.f) ? v.x : (__expf(v.x) - 1.f);
        v.y = (v.y > 0.f) ? v.y : (__expf(v.y) - 1.f);
        v.z = (v.z > 0.f) ? v.z : (__expf(v.z) - 1.f);
        v.w = (v.w > 0.f) ? v.w : (__expf(v.w) - 1.f);
        ((float4*)hs)[j] = v;
    }
    __syncthreads();
    float acc[8] = {0.f, 0.f, 0.f, 0.f, 0.f, 0.f, 0.f, 0.f};
    #pragma unroll 4
    for (int k4 = 0; k4 < 32; k4++) {
        float w0 = W2[(k4 * 4 + 0) * 32 + l];
        float w1 = W2[(k4 * 4 + 1) * 32 + l];
        float w2v = W2[(k4 * 4 + 2) * 32 + l];
        float w3 = W2[(k4 * 4 + 3) * 32 + l];
        #pragma unroll
        for (int i = 0; i < 8; i++) {
            float4 xv = ((const float4*)hs)[(w * 8 + i) * 32 + k4];
            acc[i] += xv.x * w0 + xv.y * w1 + xv.z * w2v + xv.w * w3;
        }
    }
    float cs = a2s[l], cd = a2d[l];
    #pragma unroll
    for (int i = 0; i < 8; i++) {
        int n = base + w * 8 + i;
        if (n >= NN) break;
        float a = acc[i];
        g_h2h[(long long)n * CC + l] = __float2half_rn(a);
        float ps = a * cs;
        float pd = a * cd;
        #pragma unroll
        for (int o = 16; o > 0; o >>= 1) {
            ps += __shfl_down_sync(0xffffffffu, ps, o);
            pd += __shfl_down_sync(0xffffffffu, pd, o);
        }
        if (l == 0) { g_als2[n] = ps; g_ald2[n] = pd; }
    }
}

// fused softmax + aggregation + bias + ELU, warp per dst node; 8-lane edge groups
__global__ void __launch_bounds__(256) k_agg2(const float* __restrict__ b2,
                                              float* __restrict__ out) {
    __shared__ int   ss[8 * 32];
    __shared__ float sp[8 * 32];
    int tid = threadIdx.x;
    int w = tid >> 5, l = tid & 31;
    int n = blockIdx.x * 8 + w;
    if (n >= NN) return;
    int start = g_rowptr[n], end = g_rowptr[n + 1];
    float ad = g_ald2[n];
    int g = l >> 3, q = l & 7;
    float z = 0.f;
    float4 acc = make_float4(0.f, 0.f, 0.f, 0.f);
    for (int base = start; base < end; base += 32) {
        int j = base + l;
        float p = 0.f;
        int s = 0;
        if (j < end) {
            int2 cs = g_csr[j];
            s = cs.x;
            float v = g_als2[cs.x] + ad + g_ale2[cs.y];
            v = (v > 0.f) ? v : 0.2f * v;
            p = __expf(v);
            z += p;
            g_e2[cs.y] = p;                 // unnormalized; rescaled in k_tail
        }
        ss[w * 32 + l] = s;
        sp[w * 32 + l] = p;
        __syncwarp();
        int cnt = min(32, end - base);
        for (int t4 = 0; t4 < cnt; t4 += 4) {
            int t = t4 + g;
            if (t < cnt) {
                int sv = ss[w * 32 + t];
                float pw = sp[w * 32 + t];
                float4 f = unpack4h(((const uint2*)g_h2h)[(long long)sv * 8 + q]);
                acc.x += pw * f.x; acc.y += pw * f.y;
                acc.z += pw * f.z; acc.w += pw * f.w;
            }
        }
        __syncwarp();
    }
    #pragma unroll
    for (int o = 16; o > 0; o >>= 1) z += __shfl_xor_sync(0xffffffffu, z, o);
    acc.x += __shfl_xor_sync(0xffffffffu, acc.x, 8);
    acc.y += __shfl_xor_sync(0xffffffffu, acc.y, 8);
    acc.z += __shfl_xor_sync(0xffffffffu, acc.z, 8);
    acc.w += __shfl_xor_sync(0xffffffffu, acc.w, 8);
    acc.x += __shfl_xor_sync(0xffffffffu, acc.x, 16);
    acc.y += __shfl_xor_sync(0xffffffffu, acc.y, 16);
    acc.z += __shfl_xor_sync(0xffffffffu, acc.z, 16);
    acc.w += __shfl_xor_sync(0xffffffffu, acc.w, 16);
    if (l == 0) g_z2[n] = z;
    if (l < 8) {
        float inv = 1.f / z;
        float4 bb = ((const float4*)b2)[q];
        float4 o4;
        o4.x = acc.x * inv + bb.x; o4.x = (o4.x > 0.f) ? o4.x : (__expf(o4.x) - 1.f);
        o4.y = acc.y * inv + bb.y; o4.y = (o4.y > 0.f) ? o4.y : (__expf(o4.y) - 1.f);
        o4.z = acc.z * inv + bb.z; o4.z = (o4.z > 0.f) ? o4.z : (__expf(o4.z) - 1.f);
        o4.w = acc.w * inv + bb.w; o4.w = (o4.w > 0.f) ? o4.w : (__expf(o4.w) - 1.f);
        ((float4*)out)[(long long)n * 8 + q] = o4;
    }
}

// edge_index (as float) + normalized alpha outputs
__global__ void k_tail(const int* __restrict__ ei, float* __restrict__ out,
                       int has_idx, int has_alpha) {
    int e = blockIdx.x * blockDim.x + threadIdx.x;
    if (e >= EP) return;
    int s, d;
    if (e < EE) { s = ei[e]; d = ei[EE + e]; } else { s = d = e - EE; }
    if (has_idx) {
        out[(long long)NN * CC + e] = (float)s;
        out[(long long)NN * CC + EP + e] = (float)d;
    }
    if (has_alpha) out[(long long)NN * CC + 2LL * EP + e] = g_e2[e] / g_z2[d];
}

extern "C" void kernel_launch(void* const* d_in, const int* in_sizes, int n_in,
                              void* d_out, int out_size) {
    const float* x    = (const float*)d_in[0];
    const int*   ei   = (const int*)d_in[1];
    const float* ea   = (const float*)d_in[2];
    const float* W1   = (const float*)d_in[3];
    const float* W1e  = (const float*)d_in[4];
    const float* a1s  = (const float*)d_in[5];
    const float* a1d  = (const float*)d_in[6];
    const float* a1e  = (const float*)d_in[7];
    const float* b1   = (const float*)d_in[8];
    const float* W2   = (const float*)d_in[9];
    const float* W2e  = (const float*)d_in[10];
    const float* a2s  = (const float*)d_in[11];
    const float* a2d  = (const float*)d_in[12];
    const float* a2e  = (const float*)d_in[13];
    const float* b2   = (const float*)d_in[14];
    float* out = (float*)d_out;

    int has_idx   = (out_size >= NN * CC + 2 * EP) ? 1 : 0;
    int has_alpha = (out_size >= NN * CC + 2 * EP + EP) ? 1 : 0;

    k_init<<<512, 256>>>();
    k_v<<<1, 96>>>(W1e, a1e, W2e, a2e);
    k_fused1<<<GEMM_BLOCKS + DEG_BLOCKS, 256>>>(x, W1, a1s, a1d, ei, ea);
    k_ale_self<<<(NN + 255) / 256, 256>>>();
    k_scan1<<<NB_SCAN, SCAN_B>>>();
    k_scan2<<<1, 256>>>();
    k_scan3<<<(NN + 255) / 256, 256>>>();
    k_fill<<<(EP + 255) / 256, 256>>>(ei);
    k_agg1<<<(NN + 7) / 8, 256>>>();
    k_node2<<<(NN + 63) / 64, 256>>>(b1, W2, a2s, a2d);
    k_agg2<<<(NN + 7) / 8, 256>>>(b2, out);
    k_tail<<<(EP + 255) / 256, 256>>>(ei, out, has_idx, has_alpha);
}